// round 1
// baseline (speedup 1.0000x reference)
#include <cuda_runtime.h>
#include <cuda_bf16.h>
#include <cstdint>

#define Bsz 2
#define Ssz 4096
#define Hsz 16
#define DK  128
#define CC  64
#define NCH (Ssz/CC)      // 64 chunks
#define BH  (Bsz*Hsz)     // 32
#define P1PD 129          // phase1 smem row pad (bank spread for 16-fan reads)
#define P2PD 132          // phase2 smem row pad (float4-aligned)
#define ATPD 68
#define SPLIT 4
#define DVS (DK/SPLIT)    // 32

// -------- scratch (device globals: allocation-free rule) --------
__device__ float g_qn[(size_t)BH*Ssz*DK];   // normalized+scaled q
__device__ float g_kn[(size_t)BH*Ssz*DK];   // normalized k
__device__ float g_u [(size_t)BH*Ssz*DK];   // Tinv @ (v*beta)
__device__ float g_w [(size_t)BH*Ssz*DK];   // Tinv @ (k*beta*exp(gcs))  (kcd)
__device__ float g_at[(size_t)BH*Ssz*CC];   // intra-chunk attn (tril, decayed)
__device__ float g_gc[(size_t)BH*Ssz];      // within-chunk cumsum of g

struct P1S {
  float qn[CC][P1PD];
  float kn[CC][P1PD];
  float x [CC][2*DK];
  float A [CC][CC];
  float gcs[CC];
  float bet[CC];
  float eg[CC];    // exp(gcs)
  float er[CC];    // exp(-gcs)
  float ebg[CC];   // beta*exp(gcs)
};

struct P2S {
  float st[DK][DVS];
  float qn[CC][P2PD];
  float kn[CC][P2PD];
  float kc[CC][P2PD];
  float uu[CC][DVS];
  float at[CC][ATPD];
  float vn[CC][DVS];
  float gcs[CC];
  float w [CC];    // exp(g_last - gcs)
  float eg[CC];    // exp(gcs)
};

// ================= Phase 1: per-chunk precompute (grid = BH*NCH) =================
__global__ void __launch_bounds__(256, 1) phase1_kernel(
    const float* __restrict__ q, const float* __restrict__ k,
    const float* __restrict__ v, const float* __restrict__ g,
    const float* __restrict__ beta)
{
  extern __shared__ char smraw[];
  P1S& s = *reinterpret_cast<P1S*>(smraw);
  const int t    = threadIdx.x;
  const int lane = t & 31;
  const int warp = t >> 5;
  const int cid = blockIdx.x;
  const int bh = cid / NCH, n = cid % NCH;
  const int b = bh / Hsz, h = bh % Hsz;
  const int s0 = n * CC;

  // ---- load g, beta; inclusive scan of g over the chunk ----
  if (t < CC) {
    s.bet[t] = beta[(size_t)(b*Ssz + s0 + t)*Hsz + h];
    s.gcs[t] = g   [(size_t)(b*Ssz + s0 + t)*Hsz + h];
  }
  __syncthreads();
  if (t < CC) {
    float x = s.gcs[t];
    #pragma unroll
    for (int o = 1; o < 32; o <<= 1) {
      float y = __shfl_up_sync(0xffffffffu, x, o);
      if (lane >= o) x += y;
    }
    s.gcs[t] = x;
  }
  __syncthreads();
  if (t >= 32 && t < CC) s.gcs[t] += s.gcs[31];  // combine the two warps

  // ---- normalize q,k rows (8 warps x 8 rows), write smem + global ----
  for (int r = warp; r < CC; r += 8) {
    const size_t base = ((size_t)(b*Ssz + s0 + r)*Hsz + h)*DK;
    float kv[4], qv[4];
    float ssk = 0.f, ssq = 0.f;
    #pragma unroll
    for (int i = 0; i < 4; i++) {
      kv[i] = k[base + lane + 32*i]; ssk = fmaf(kv[i], kv[i], ssk);
      qv[i] = q[base + lane + 32*i]; ssq = fmaf(qv[i], qv[i], ssq);
    }
    #pragma unroll
    for (int o = 16; o; o >>= 1) {
      ssk += __shfl_xor_sync(0xffffffffu, ssk, o);
      ssq += __shfl_xor_sync(0xffffffffu, ssq, o);
    }
    const float rk = rsqrtf(ssk + 1e-6f);
    const float rq = rsqrtf(ssq + 1e-6f) * 0.08838834764831845f;  // * Dk^-0.5
    const size_t ob = ((size_t)bh*Ssz + s0 + r)*DK;
    #pragma unroll
    for (int i = 0; i < 4; i++) {
      const float kk = kv[i]*rk, qq = qv[i]*rq;
      s.kn[r][lane+32*i] = kk; g_kn[ob + lane + 32*i] = kk;
      s.qn[r][lane+32*i] = qq; g_qn[ob + lane + 32*i] = qq;
    }
  }
  __syncthreads();

  // ---- precompute exponentials once (MUFU is slow: 0.5/cyc/SM) ----
  if (t < CC) {
    const float gi = s.gcs[t];
    const float e  = __expf(gi);
    s.eg[t]  = e;
    s.er[t]  = __expf(-gi);
    s.ebg[t] = s.bet[t] * e;
  }
  __syncthreads();

  // ---- x init: thread t owns column t of [v*beta | kn*beta*exp(gcs)] ----
  if (t < DK) {
    #pragma unroll 4
    for (int i = 0; i < CC; i++)
      s.x[i][t] = v[((size_t)(b*Ssz + s0 + i)*Hsz + h)*DK + t] * s.bet[i];
  } else {
    const int d = t - DK;
    #pragma unroll 4
    for (int i = 0; i < CC; i++)
      s.x[i][t] = s.kn[i][d] * s.ebg[i];
  }

  // ---- A (strict lower, for the solve) and attn (tril, stored to global) ----
  {
    const int ti = t >> 4, tj = t & 15;
    float accA[4][4] = {}, accT[4][4] = {};
    #pragma unroll 4
    for (int d = 0; d < DK; d++) {
      float kd[4], qd[4], kj[4];
      #pragma unroll
      for (int a = 0; a < 4; a++) {
        kd[a] = s.kn[ti*4+a][d];
        qd[a] = s.qn[ti*4+a][d];
        kj[a] = s.kn[tj*4+a][d];
      }
      #pragma unroll
      for (int a = 0; a < 4; a++)
        #pragma unroll
        for (int c = 0; c < 4; c++) {
          accA[a][c] = fmaf(kd[a], kj[c], accA[a][c]);
          accT[a][c] = fmaf(qd[a], kj[c], accT[a][c]);
        }
    }
    #pragma unroll
    for (int a = 0; a < 4; a++) {
      const int i = ti*4 + a;
      const float bi = s.bet[i];
      const float ei = s.eg[i];
      #pragma unroll
      for (int c = 0; c < 4; c++) {
        const int j = tj*4 + c;
        const float dec = ei * s.er[j];             // exp(gcs_i - gcs_j)
        s.A[i][j] = (j < i) ? bi*accA[a][c]*dec : 0.f;
        g_at[((size_t)bh*Ssz + s0 + i)*CC + j] = (j <= i) ? accT[a][c]*dec : 0.f;
      }
    }
  }
  __syncthreads();

  // ---- forward substitution: (I+A) x' = x, column-independent per thread ----
  {
    #pragma unroll 1
    for (int i = 1; i < CC; i++) {
      float acc = s.x[i][t];
      #pragma unroll 1
      for (int j = 0; j < i; j++) acc = fmaf(-s.A[i][j], s.x[j][t], acc);
      s.x[i][t] = acc;
    }
  }

  // ---- write u, kcd, gcs ----
  {
    const size_t ob = ((size_t)bh*Ssz + s0)*DK;
    if (t < DK) {
      #pragma unroll 4
      for (int i = 0; i < CC; i++) g_u[ob + (size_t)i*DK + t] = s.x[i][t];
    } else {
      const int d = t - DK;
      #pragma unroll 4
      for (int i = 0; i < CC; i++) g_w[ob + (size_t)i*DK + d] = s.x[i][t];
    }
  }
  if (t < CC) g_gc[(size_t)bh*Ssz + s0 + t] = s.gcs[t];
}

// ================= Phase 2: sequential scan (grid = BH*SPLIT, Dv-split) =================
__global__ void __launch_bounds__(256, 1) phase2_kernel(float* __restrict__ out)
{
  extern __shared__ char smraw[];
  P2S& s = *reinterpret_cast<P2S*>(smraw);
  const int t  = threadIdx.x;
  const int bh = blockIdx.x / SPLIT;
  const int sp = blockIdx.x % SPLIT;
  const int b = bh / Hsz, h = bh % Hsz;
  const int v0 = sp * DVS;

  for (int i = t; i < DK*DVS; i += 256) (&s.st[0][0])[i] = 0.f;

  const int i0 = (t >> 4) * 4;   // 4-row tile for B/C stages
  const int vv = (t & 15) * 2;   // 2-col tile
  const int d0 = (t >> 4) * 8;   // 8-row tile for D stage

  for (int n = 0; n < NCH; n++) {
    const size_t rb = (size_t)bh*Ssz + n*CC;
    __syncthreads();  // prev-iter state/vn reads done before buffer overwrite

    // ---- stage A: load chunk tiles ----
    {
      const float4* gq = reinterpret_cast<const float4*>(g_qn + rb*DK);
      const float4* gk = reinterpret_cast<const float4*>(g_kn + rb*DK);
      const float4* gw = reinterpret_cast<const float4*>(g_w  + rb*DK);
      #pragma unroll 2
      for (int idx = t; idx < CC*32; idx += 256) {
        const int r = idx >> 5, c4 = idx & 31;
        *reinterpret_cast<float4*>(&s.qn[r][c4*4]) = gq[idx];
        *reinterpret_cast<float4*>(&s.kn[r][c4*4]) = gk[idx];
        *reinterpret_cast<float4*>(&s.kc[r][c4*4]) = gw[idx];
      }
      #pragma unroll 2
      for (int idx = t; idx < CC*DVS; idx += 256) {
        const int r = idx >> 5, c = idx & 31;
        s.uu[r][c] = g_u[(rb + r)*DK + v0 + c];
      }
      const float4* ga = reinterpret_cast<const float4*>(g_at + rb*CC);
      #pragma unroll 2
      for (int idx = t; idx < CC*16; idx += 256) {
        const int r = idx >> 4, c4 = idx & 15;
        *reinterpret_cast<float4*>(&s.at[r][c4*4]) = ga[idx];
      }
      if (t < CC) s.gcs[t] = g_gc[rb + t];
    }
    __syncthreads();
    if (t < CC) {
      s.w[t]  = __expf(s.gcs[CC-1] - s.gcs[t]);
      s.eg[t] = __expf(s.gcs[t]);
    }

    // ---- stage B: v_new = u - kcd@state ; o_part = (q*eg)@state ----
    float oacc[4][2];
    {
      float va[4][2];
      #pragma unroll
      for (int a = 0; a < 4; a++) { va[a][0]=va[a][1]=0.f; oacc[a][0]=oacc[a][1]=0.f; }
      #pragma unroll 2
      for (int d = 0; d < DK; d++) {
        const float st0 = s.st[d][vv], st1 = s.st[d][vv+1];
        #pragma unroll
        for (int a = 0; a < 4; a++) {
          const float kcv = s.kc[i0+a][d];
          const float qv  = s.qn[i0+a][d];
          va[a][0]   = fmaf(-kcv, st0, va[a][0]);
          va[a][1]   = fmaf(-kcv, st1, va[a][1]);
          oacc[a][0] = fmaf( qv,  st0, oacc[a][0]);
          oacc[a][1] = fmaf( qv,  st1, oacc[a][1]);
        }
      }
      #pragma unroll
      for (int a = 0; a < 4; a++) {
        const int i = i0 + a;
        s.vn[i][vv]   = s.uu[i][vv]   + va[a][0];
        s.vn[i][vv+1] = s.uu[i][vv+1] + va[a][1];
        const float eg = s.eg[i];
        oacc[a][0] *= eg; oacc[a][1] *= eg;
      }
    }
    __syncthreads();

    // ---- stage C: o += attn @ v_new ; store ----
    {
      #pragma unroll 2
      for (int j = 0; j < CC; j++) {
        const float w0 = s.vn[j][vv], w1 = s.vn[j][vv+1];
        #pragma unroll
        for (int a = 0; a < 4; a++) {
          const float av = s.at[i0+a][j];   // 0 above diagonal
          oacc[a][0] = fmaf(av, w0, oacc[a][0]);
          oacc[a][1] = fmaf(av, w1, oacc[a][1]);
        }
      }
      #pragma unroll
      for (int a = 0; a < 4; a++) {
        const int i = i0 + a;
        float2 o2; o2.x = oacc[a][0]; o2.y = oacc[a][1];
        *reinterpret_cast<float2*>(out + ((size_t)(b*Ssz + n*CC + i)*Hsz + h)*DK + v0 + vv) = o2;
      }
    }

    // ---- stage D: state = el*state + (k*exp(g_last-gcs))^T @ v_new ----
    {
      const float el = s.eg[CC-1];
      float acc[8][2];
      #pragma unroll
      for (int a = 0; a < 8; a++) { acc[a][0]=0.f; acc[a][1]=0.f; }
      #pragma unroll 2
      for (int i = 0; i < CC; i++) {
        const float wi = s.w[i];
        const float w0 = s.vn[i][vv]*wi, w1 = s.vn[i][vv+1]*wi;
        #pragma unroll
        for (int a = 0; a < 8; a++) {
          const float kv = s.kn[i][d0+a];
          acc[a][0] = fmaf(kv, w0, acc[a][0]);
          acc[a][1] = fmaf(kv, w1, acc[a][1]);
        }
      }
      #pragma unroll
      for (int a = 0; a < 8; a++) {
        s.st[d0+a][vv]   = s.st[d0+a][vv]  *el + acc[a][0];
        s.st[d0+a][vv+1] = s.st[d0+a][vv+1]*el + acc[a][1];
      }
    }
  }
}

// ================= launch =================
extern "C" void kernel_launch(void* const* d_in, const int* in_sizes, int n_in,
                              void* d_out, int out_size) {
  const float* q    = (const float*)d_in[0];
  const float* k    = (const float*)d_in[1];
  const float* v    = (const float*)d_in[2];
  const float* g    = (const float*)d_in[3];
  const float* beta = (const float*)d_in[4];
  float* out = (float*)d_out;

  cudaFuncSetAttribute((const void*)phase1_kernel,
                       cudaFuncAttributeMaxDynamicSharedMemorySize, (int)sizeof(P1S));
  cudaFuncSetAttribute((const void*)phase2_kernel,
                       cudaFuncAttributeMaxDynamicSharedMemorySize, (int)sizeof(P2S));

  phase1_kernel<<<BH*NCH, 256, sizeof(P1S)>>>(q, k, v, g, beta);
  phase2_kernel<<<BH*SPLIT, 256, sizeof(P2S)>>>(out);
}

// round 2
// speedup vs baseline: 1.8615x; 1.8615x over previous
#include <cuda_runtime.h>
#include <cuda_bf16.h>
#include <cstdint>

#define Bsz 2
#define Ssz 4096
#define Hsz 16
#define DK  128
#define CC  64
#define NCH (Ssz/CC)      // 64 chunks
#define BH  (Bsz*Hsz)     // 32
#define CCP 68            // phase1 transposed row pad (mult of 4; 4-way scatter worst case)
#define SPLIT 4
#define DVS (DK/SPLIT)    // 32

// -------- scratch (device globals: allocation-free rule) --------
__device__ float g_qg[(size_t)BH*Ssz*DK];   // normalized q * Dk^-0.5 * exp(gcs)
__device__ float g_kn[(size_t)BH*Ssz*DK];   // normalized k
__device__ float g_u [(size_t)BH*Ssz*DK];   // Tinv @ (v*beta)
__device__ float g_w [(size_t)BH*Ssz*DK];   // Tinv @ (k*beta*exp(gcs))  (kcd)
__device__ float g_at[(size_t)BH*Ssz*CC];   // intra-chunk attn (tril, decayed)
__device__ float g_gc[(size_t)BH*Ssz];      // within-chunk cumsum of g

struct P1S {
  float knT[DK][CCP];   // transposed: [d][row]
  float qgT[DK][CCP];   // transposed, q scaled by Dk^-0.5 * exp(gcs)
  float A  [CC][CC];    // strict-lower, zero elsewhere
  float gcs[CC];
  float bet[CC];
  float eg[CC];    // exp(gcs)
  float er[CC];    // exp(-gcs)
  float ebg[CC];   // beta*exp(gcs)
};

struct P2S {
  float st[DK][DVS];
  float qg[CC][DK];
  float kn[CC][DK];
  float kc[CC][DK];
  float uu[CC][DVS];
  float at[CC][CC];
  float vn[CC][DVS];
  float gcs[CC];
  float w [CC];    // exp(g_last - gcs)
  float elv;       // exp(g_last)
};

// ================= Phase 1: per-chunk precompute (grid = BH*NCH) =================
__global__ void __launch_bounds__(256, 2) phase1_kernel(
    const float* __restrict__ q, const float* __restrict__ k,
    const float* __restrict__ v, const float* __restrict__ g,
    const float* __restrict__ beta)
{
  extern __shared__ char smraw[];
  P1S& s = *reinterpret_cast<P1S*>(smraw);
  const int t    = threadIdx.x;
  const int lane = t & 31;
  const int warp = t >> 5;
  const int cid = blockIdx.x;
  const int bh = cid / NCH, n = cid % NCH;
  const int b = bh / Hsz, h = bh % Hsz;
  const int s0 = n * CC;

  // ---- load g, beta; inclusive scan of g over the chunk ----
  if (t < CC) {
    s.bet[t] = beta[(size_t)(b*Ssz + s0 + t)*Hsz + h];
    s.gcs[t] = g   [(size_t)(b*Ssz + s0 + t)*Hsz + h];
  }
  __syncthreads();
  if (t < CC) {
    float x = s.gcs[t];
    #pragma unroll
    for (int o = 1; o < 32; o <<= 1) {
      float y = __shfl_up_sync(0xffffffffu, x, o);
      if (lane >= o) x += y;
    }
    s.gcs[t] = x;
  }
  __syncthreads();
  if (t < CC) {
    float gi = s.gcs[t];
    if (t >= 32) { gi += s.gcs[31]; s.gcs[t] = gi; }
    const float e = __expf(gi);
    s.eg[t]  = e;
    s.er[t]  = __expf(-gi);
    s.ebg[t] = s.bet[t] * e;
    g_gc[(size_t)bh*Ssz + s0 + t] = gi;
  }
  __syncthreads();

  // ---- normalize q,k rows (8 warps x 8 rows), scatter to transposed smem + global ----
  for (int r = warp; r < CC; r += 8) {
    const size_t base = ((size_t)(b*Ssz + s0 + r)*Hsz + h)*DK;
    float kv[4], qv[4];
    float ssk = 0.f, ssq = 0.f;
    #pragma unroll
    for (int i = 0; i < 4; i++) {
      kv[i] = k[base + lane + 32*i]; ssk = fmaf(kv[i], kv[i], ssk);
      qv[i] = q[base + lane + 32*i]; ssq = fmaf(qv[i], qv[i], ssq);
    }
    #pragma unroll
    for (int o = 16; o; o >>= 1) {
      ssk += __shfl_xor_sync(0xffffffffu, ssk, o);
      ssq += __shfl_xor_sync(0xffffffffu, ssq, o);
    }
    const float rk = rsqrtf(ssk + 1e-6f);
    const float rq = rsqrtf(ssq + 1e-6f) * 0.08838834764831845f * s.eg[r]; // Dk^-.5 * e^gcs
    const size_t ob = ((size_t)bh*Ssz + s0 + r)*DK;
    #pragma unroll
    for (int i = 0; i < 4; i++) {
      const int d = lane + 32*i;
      const float kk = kv[i]*rk, qq = qv[i]*rq;
      s.knT[d][r] = kk; g_kn[ob + d] = kk;
      s.qgT[d][r] = qq; g_qg[ob + d] = qq;
    }
  }
  __syncthreads();

  // ---- GEMM: A = strict-lower(kb k^T dec), attn = tril(qg k^T e^{-g_j}) ----
  {
    const int ti = t >> 4, tj = t & 15;
    const size_t atb = ((size_t)bh*Ssz + s0)*CC;
    if (tj <= ti) {
      float accA[4][4] = {}, accT[4][4] = {};
      #pragma unroll 4
      for (int d = 0; d < DK; d++) {
        const float4 kd4 = *reinterpret_cast<const float4*>(&s.knT[d][ti*4]);
        const float4 qd4 = *reinterpret_cast<const float4*>(&s.qgT[d][ti*4]);
        const float4 kj4 = *reinterpret_cast<const float4*>(&s.knT[d][tj*4]);
        const float kd[4] = {kd4.x, kd4.y, kd4.z, kd4.w};
        const float qd[4] = {qd4.x, qd4.y, qd4.z, qd4.w};
        const float kj[4] = {kj4.x, kj4.y, kj4.z, kj4.w};
        #pragma unroll
        for (int a = 0; a < 4; a++)
          #pragma unroll
          for (int c = 0; c < 4; c++) {
            accA[a][c] = fmaf(kd[a], kj[c], accA[a][c]);
            accT[a][c] = fmaf(qd[a], kj[c], accT[a][c]);
          }
      }
      const float erj[4] = {s.er[tj*4], s.er[tj*4+1], s.er[tj*4+2], s.er[tj*4+3]};
      #pragma unroll
      for (int a = 0; a < 4; a++) {
        const int i = ti*4 + a;
        const float bei = s.bet[i] * s.eg[i];
        float4 av, tv;
        float* ap = &av.x; float* tp = &tv.x;
        #pragma unroll
        for (int c = 0; c < 4; c++) {
          const int j = tj*4 + c;
          ap[c] = (j < i)  ? accA[a][c]*bei*erj[c] : 0.f;
          tp[c] = (j <= i) ? accT[a][c]*erj[c]     : 0.f;
        }
        *reinterpret_cast<float4*>(&s.A[i][tj*4]) = av;
        *reinterpret_cast<float4*>(&g_at[atb + (size_t)i*CC + tj*4]) = tv;
      }
    } else {
      const float4 z = {0.f, 0.f, 0.f, 0.f};
      #pragma unroll
      for (int a = 0; a < 4; a++) {
        const int i = ti*4 + a;
        *reinterpret_cast<float4*>(&s.A[i][tj*4]) = z;
        *reinterpret_cast<float4*>(&g_at[atb + (size_t)i*CC + tj*4]) = z;
      }
    }
  }
  __syncthreads();

  // ---- x init (registers): column t of [v*beta | kn*beta*e^gcs] ----
  float xr[CC];
  if (t < DK) {
    #pragma unroll 8
    for (int i = 0; i < CC; i++)
      xr[i] = v[((size_t)(b*Ssz + s0 + i)*Hsz + h)*DK + t] * s.bet[i];
  } else {
    const int d = t - DK;
    #pragma unroll 8
    for (int i = 0; i < CC; i++)
      xr[i] = s.knT[d][i] * s.ebg[i];
  }

  // ---- forward substitution in registers: (I+A) x' = x ----
  // A has zeros on/above diagonal, so full quads are safe.
  #pragma unroll
  for (int i = 1; i < CC; i++) {
    const float4* Ai = reinterpret_cast<const float4*>(&s.A[i][0]);
    float a0 = 0.f, a1 = 0.f, a2 = 0.f, a3 = 0.f;
    const int nq = (i + 3) >> 2;
    #pragma unroll
    for (int j4 = 0; j4 < nq; j4++) {
      const float4 av = Ai[j4];
      a0 = fmaf(av.x, xr[j4*4+0], a0);
      a1 = fmaf(av.y, xr[j4*4+1], a1);
      a2 = fmaf(av.z, xr[j4*4+2], a2);
      a3 = fmaf(av.w, xr[j4*4+3], a3);
    }
    xr[i] -= (a0 + a1) + (a2 + a3);
  }

  // ---- write u (cols 0..127) and kcd (cols 128..255) ----
  {
    const size_t ob = ((size_t)bh*Ssz + s0)*DK;
    if (t < DK) {
      #pragma unroll 8
      for (int i = 0; i < CC; i++) g_u[ob + (size_t)i*DK + t] = xr[i];
    } else {
      const int d = t - DK;
      #pragma unroll 8
      for (int i = 0; i < CC; i++) g_w[ob + (size_t)i*DK + d] = xr[i];
    }
  }
}

// ================= Phase 2: sequential scan (grid = BH*SPLIT, Dv-split) =================
__global__ void __launch_bounds__(256, 1) phase2_kernel(float* __restrict__ out)
{
  extern __shared__ char smraw[];
  P2S& s = *reinterpret_cast<P2S*>(smraw);
  const int t  = threadIdx.x;
  const int bh = blockIdx.x / SPLIT;
  const int sp = blockIdx.x % SPLIT;
  const int b = bh / Hsz, h = bh % Hsz;
  const int v0 = sp * DVS;

  for (int i = t; i < DK*DVS; i += 256) (&s.st[0][0])[i] = 0.f;

  const int i0 = (t >> 4) * 4;   // 4-row tile for B/C stages
  const int vv = (t & 15) * 2;   // 2-col tile
  const int d0 = (t >> 4) * 8;   // 8-row tile for D stage

  for (int n = 0; n < NCH; n++) {
    const size_t rb = (size_t)bh*Ssz + n*CC;
    __syncthreads();  // prev-iter state/vn reads done before buffer overwrite

    // ---- stage A: load chunk tiles ----
    {
      const float4* gq = reinterpret_cast<const float4*>(g_qg + rb*DK);
      const float4* gk = reinterpret_cast<const float4*>(g_kn + rb*DK);
      const float4* gw = reinterpret_cast<const float4*>(g_w  + rb*DK);
      #pragma unroll 2
      for (int idx = t; idx < CC*32; idx += 256) {
        const int r = idx >> 5, c4 = idx & 31;
        *reinterpret_cast<float4*>(&s.qg[r][c4*4]) = gq[idx];
        *reinterpret_cast<float4*>(&s.kn[r][c4*4]) = gk[idx];
        *reinterpret_cast<float4*>(&s.kc[r][c4*4]) = gw[idx];
      }
      #pragma unroll 2
      for (int idx = t; idx < CC*8; idx += 256) {
        const int r = idx >> 3, c4 = idx & 7;
        *reinterpret_cast<float4*>(&s.uu[r][c4*4]) =
          *reinterpret_cast<const float4*>(&g_u[(rb + r)*DK + v0 + c4*4]);
      }
      const float4* ga = reinterpret_cast<const float4*>(g_at + rb*CC);
      #pragma unroll 2
      for (int idx = t; idx < CC*16; idx += 256) {
        const int r = idx >> 4, c4 = idx & 15;
        *reinterpret_cast<float4*>(&s.at[r][c4*4]) = ga[idx];
      }
      if (t < CC) s.gcs[t] = g_gc[rb + t];
    }
    __syncthreads();
    if (t < CC) {
      const float gl = s.gcs[CC-1];
      s.w[t] = __expf(gl - s.gcs[t]);
      if (t == CC-1) s.elv = __expf(gl);
    }
    // (s.w/s.elv are consumed in stage D, after the B->C barrier)

    // ---- stage B: v_new = u - kcd@state ; o_part = qg@state ----
    float oacc[4][2];
    {
      float va[4][2];
      #pragma unroll
      for (int a = 0; a < 4; a++) { va[a][0]=va[a][1]=0.f; oacc[a][0]=oacc[a][1]=0.f; }
      #pragma unroll 2
      for (int d = 0; d < DK; d += 4) {
        float stv[4][2];
        #pragma unroll
        for (int m = 0; m < 4; m++) {
          const float2 s2 = *reinterpret_cast<const float2*>(&s.st[d+m][vv]);
          stv[m][0] = s2.x; stv[m][1] = s2.y;
        }
        #pragma unroll
        for (int a = 0; a < 4; a++) {
          const float4 kc4 = *reinterpret_cast<const float4*>(&s.kc[i0+a][d]);
          const float4 qg4 = *reinterpret_cast<const float4*>(&s.qg[i0+a][d]);
          const float kcv[4] = {kc4.x, kc4.y, kc4.z, kc4.w};
          const float qgv[4] = {qg4.x, qg4.y, qg4.z, qg4.w};
          #pragma unroll
          for (int m = 0; m < 4; m++) {
            va[a][0]   = fmaf(-kcv[m], stv[m][0], va[a][0]);
            va[a][1]   = fmaf(-kcv[m], stv[m][1], va[a][1]);
            oacc[a][0] = fmaf( qgv[m], stv[m][0], oacc[a][0]);
            oacc[a][1] = fmaf( qgv[m], stv[m][1], oacc[a][1]);
          }
        }
      }
      #pragma unroll
      for (int a = 0; a < 4; a++) {
        const int i = i0 + a;
        float2 v2;
        v2.x = s.uu[i][vv]   + va[a][0];
        v2.y = s.uu[i][vv+1] + va[a][1];
        *reinterpret_cast<float2*>(&s.vn[i][vv]) = v2;
      }
    }
    __syncthreads();

    // ---- stage C: o += attn @ v_new ; store ----
    {
      #pragma unroll 2
      for (int j = 0; j < CC; j += 4) {
        float vnv[4][2];
        #pragma unroll
        for (int m = 0; m < 4; m++) {
          const float2 v2 = *reinterpret_cast<const float2*>(&s.vn[j+m][vv]);
          vnv[m][0] = v2.x; vnv[m][1] = v2.y;
        }
        #pragma unroll
        for (int a = 0; a < 4; a++) {
          const float4 at4 = *reinterpret_cast<const float4*>(&s.at[i0+a][j]);
          const float atv[4] = {at4.x, at4.y, at4.z, at4.w};
          #pragma unroll
          for (int m = 0; m < 4; m++) {
            oacc[a][0] = fmaf(atv[m], vnv[m][0], oacc[a][0]);
            oacc[a][1] = fmaf(atv[m], vnv[m][1], oacc[a][1]);
          }
        }
      }
      #pragma unroll
      for (int a = 0; a < 4; a++) {
        const int i = i0 + a;
        float2 o2; o2.x = oacc[a][0]; o2.y = oacc[a][1];
        *reinterpret_cast<float2*>(out + ((size_t)(b*Ssz + n*CC + i)*Hsz + h)*DK + v0 + vv) = o2;
      }
    }

    // ---- stage D: state = el*state + (k*exp(g_last-gcs))^T @ v_new ----
    {
      const float el = s.elv;
      float acc[8][2];
      #pragma unroll
      for (int a = 0; a < 8; a++) { acc[a][0]=0.f; acc[a][1]=0.f; }
      #pragma unroll 2
      for (int i = 0; i < CC; i++) {
        const float wi = s.w[i];
        const float2 v2 = *reinterpret_cast<const float2*>(&s.vn[i][vv]);
        const float w0 = v2.x*wi, w1 = v2.y*wi;
        const float4 ka = *reinterpret_cast<const float4*>(&s.kn[i][d0]);
        const float4 kb = *reinterpret_cast<const float4*>(&s.kn[i][d0+4]);
        const float kv[8] = {ka.x, ka.y, ka.z, ka.w, kb.x, kb.y, kb.z, kb.w};
        #pragma unroll
        for (int a = 0; a < 8; a++) {
          acc[a][0] = fmaf(kv[a], w0, acc[a][0]);
          acc[a][1] = fmaf(kv[a], w1, acc[a][1]);
        }
      }
      #pragma unroll
      for (int a = 0; a < 8; a++) {
        float2 s2 = *reinterpret_cast<const float2*>(&s.st[d0+a][vv]);
        s2.x = s2.x*el + acc[a][0];
        s2.y = s2.y*el + acc[a][1];
        *reinterpret_cast<float2*>(&s.st[d0+a][vv]) = s2;
      }
    }
  }
}

// ================= launch =================
extern "C" void kernel_launch(void* const* d_in, const int* in_sizes, int n_in,
                              void* d_out, int out_size) {
  const float* q    = (const float*)d_in[0];
  const float* k    = (const float*)d_in[1];
  const float* v    = (const float*)d_in[2];
  const float* g    = (const float*)d_in[3];
  const float* beta = (const float*)d_in[4];
  float* out = (float*)d_out;

  cudaFuncSetAttribute((const void*)phase1_kernel,
                       cudaFuncAttributeMaxDynamicSharedMemorySize, (int)sizeof(P1S));
  cudaFuncSetAttribute((const void*)phase2_kernel,
                       cudaFuncAttributeMaxDynamicSharedMemorySize, (int)sizeof(P2S));

  phase1_kernel<<<BH*NCH, 256, sizeof(P1S)>>>(q, k, v, g, beta);
  phase2_kernel<<<BH*SPLIT, 256, sizeof(P2S)>>>(out);
}